// round 1
// baseline (speedup 1.0000x reference)
#include <cuda_runtime.h>
#include <math.h>
#include <float.h>

#define N_NODES 50000
#define N_EDGES 800000
#define DIM 128
#define EDIM 32

// ---------------- scratch (static device allocations) ----------------
__device__ float g_z[N_NODES * DIM];      // projected features
__device__ float g_ssrc[N_NODES];
__device__ float g_sdst[N_NODES];
__device__ float g_t[N_EDGES];            // s_e + s_src[src]
__device__ int   g_cnt[N_NODES];
__device__ int   g_off[N_NODES + 1];
__device__ int   g_cur[N_NODES];
__device__ int   g_srcp[N_EDGES];         // src ids permuted by dst
__device__ float g_tp[N_EDGES];           // t permuted by dst

__global__ void init_kernel() {
    int i = blockIdx.x * blockDim.x + threadIdx.x;
    if (i < N_NODES) g_cnt[i] = 0;
}

// ---------------- GEMM: z = nfeats @ W_fc^T ----------------
// Block: 256 threads computes 64 rows x 128 cols. Each thread: 8 rows x 4 cols.
#define FMA4(ACC, S, B) { (ACC).x += (S)*(B).x; (ACC).y += (S)*(B).y; (ACC).z += (S)*(B).z; (ACC).w += (S)*(B).w; }

__global__ __launch_bounds__(256) void gemm_kernel(const float* __restrict__ A,
                                                   const float* __restrict__ W) {
    __shared__ __align__(16) float As[64 * 32];    // [row][kk]
    __shared__ __align__(16) float Bs[32 * 132];   // [kk][j], padded

    int tid = threadIdx.x;
    int i0 = blockIdx.x * 64;
    int tx = tid & 31;      // col group: cols tx*4 .. tx*4+3
    int ty = tid >> 5;      // row group: rows ty*8 .. ty*8+7

    float4 acc[8];
#pragma unroll
    for (int r = 0; r < 8; r++) acc[r] = make_float4(0.f, 0.f, 0.f, 0.f);

    for (int kc = 0; kc < 128; kc += 32) {
        // load A chunk: 64 rows x 32 k  (512 float4, 2 per thread)
#pragma unroll
        for (int t = 0; t < 2; t++) {
            int idx = tid + t * 256;
            int row = idx >> 3, c4 = idx & 7;
            int gr = i0 + row;
            float4 v = make_float4(0.f, 0.f, 0.f, 0.f);
            if (gr < N_NODES) v = *(const float4*)&A[gr * 128 + kc + c4 * 4];
            *(float4*)&As[row * 32 + c4 * 4] = v;
        }
        // load W chunk transposed: Bs[kk][j] = W[j][kc+kk]
#pragma unroll
        for (int t = 0; t < 4; t++) {
            int idx = tid + t * 256;
            int j = idx >> 3, k4 = idx & 7;
            float4 v = *(const float4*)&W[j * 128 + kc + k4 * 4];
            Bs[(k4 * 4 + 0) * 132 + j] = v.x;
            Bs[(k4 * 4 + 1) * 132 + j] = v.y;
            Bs[(k4 * 4 + 2) * 132 + j] = v.z;
            Bs[(k4 * 4 + 3) * 132 + j] = v.w;
        }
        __syncthreads();

#pragma unroll
        for (int kk = 0; kk < 32; kk += 4) {
            float4 b0 = *(const float4*)&Bs[(kk + 0) * 132 + tx * 4];
            float4 b1 = *(const float4*)&Bs[(kk + 1) * 132 + tx * 4];
            float4 b2 = *(const float4*)&Bs[(kk + 2) * 132 + tx * 4];
            float4 b3 = *(const float4*)&Bs[(kk + 3) * 132 + tx * 4];
#pragma unroll
            for (int r = 0; r < 8; r++) {
                float4 a = *(const float4*)&As[(ty * 8 + r) * 32 + kk];
                FMA4(acc[r], a.x, b0);
                FMA4(acc[r], a.y, b1);
                FMA4(acc[r], a.z, b2);
                FMA4(acc[r], a.w, b3);
            }
        }
        __syncthreads();
    }

#pragma unroll
    for (int r = 0; r < 8; r++) {
        int gr = i0 + ty * 8 + r;
        if (gr < N_NODES) *(float4*)&g_z[gr * 128 + tx * 4] = acc[r];
    }
}

// ---------------- per-node attention projections ----------------
__global__ __launch_bounds__(256) void attn_proj_kernel(const float* __restrict__ Wattn) {
    int gid = blockIdx.x * blockDim.x + threadIdx.x;
    int node = gid >> 5;
    int lane = gid & 31;
    if (node >= N_NODES) return;
    float4 zv = *(const float4*)&g_z[node * 128 + lane * 4];
    float4 as = *(const float4*)&Wattn[lane * 4];                 // a_src
    float4 ad = *(const float4*)&Wattn[DIM + EDIM + lane * 4];    // a_dst (offset 160)
    float ps = zv.x * as.x + zv.y * as.y + zv.z * as.z + zv.w * as.w;
    float pd = zv.x * ad.x + zv.y * ad.y + zv.z * ad.z + zv.w * ad.w;
#pragma unroll
    for (int o = 16; o; o >>= 1) {
        ps += __shfl_xor_sync(0xffffffffu, ps, o);
        pd += __shfl_xor_sync(0xffffffffu, pd, o);
    }
    if (lane == 0) { g_ssrc[node] = ps; g_sdst[node] = pd; }
}

// ---------------- per-edge: s_e + s_src[src], and dst histogram ----------------
// 8 lanes per edge, float4 per lane over the 32 edge features.
__global__ __launch_bounds__(256) void edge_prep_kernel(const float* __restrict__ efeats,
                                                        const float* __restrict__ Wattn,
                                                        const int* __restrict__ src,
                                                        const int* __restrict__ dst) {
    int gid = blockIdx.x * blockDim.x + threadIdx.x;
    int e = gid >> 3;
    int l = gid & 7;
    if (e >= N_EDGES) return;
    float4 ev = *(const float4*)&efeats[e * EDIM + l * 4];
    float4 av = *(const float4*)&Wattn[DIM + l * 4];   // a_e (offset 128)
    float p = ev.x * av.x + ev.y * av.y + ev.z * av.z + ev.w * av.w;
    p += __shfl_xor_sync(0xffffffffu, p, 4);
    p += __shfl_xor_sync(0xffffffffu, p, 2);
    p += __shfl_xor_sync(0xffffffffu, p, 1);
    if (l == 0) {
        int s = src[e];
        int d = dst[e];
        g_t[e] = p + g_ssrc[s];
        atomicAdd(&g_cnt[d], 1);
    }
}

// ---------------- single-block scan: counts -> exclusive offsets ----------------
__global__ __launch_bounds__(1024) void scan_kernel() {
    __shared__ int ss[1024];
    int t = threadIdx.x;
    const int CH = (N_NODES + 1023) / 1024;   // 49
    int base = t * CH;
    int s = 0;
    for (int i = 0; i < CH; i++) {
        int idx = base + i;
        if (idx < N_NODES) s += g_cnt[idx];
    }
    ss[t] = s;
    __syncthreads();
    int incl = s;
    for (int off = 1; off < 1024; off <<= 1) {
        int v = (t >= off) ? ss[t - off] : 0;
        __syncthreads();
        incl += v;
        ss[t] = incl;
        __syncthreads();
    }
    int run = incl - s;   // exclusive prefix
    for (int i = 0; i < CH; i++) {
        int idx = base + i;
        if (idx < N_NODES) {
            g_off[idx] = run;
            g_cur[idx] = run;
            run += g_cnt[idx];
        }
    }
    if (t == 1023) g_off[N_NODES] = run;   // t=1023's chunk is past N_NODES -> run == total
}

// ---------------- scatter edges into CSR order ----------------
__global__ __launch_bounds__(256) void scatter_kernel(const int* __restrict__ src,
                                                      const int* __restrict__ dst) {
    int e = blockIdx.x * blockDim.x + threadIdx.x;
    if (e >= N_EDGES) return;
    int d = dst[e];
    int pos = atomicAdd(&g_cur[d], 1);
    g_srcp[pos] = src[e];
    g_tp[pos] = g_t[e];
}

// ---------------- warp-per-node softmax + aggregation ----------------
__global__ __launch_bounds__(256) void aggregate_kernel(float* __restrict__ h) {
    int gid = blockIdx.x * blockDim.x + threadIdx.x;
    int node = gid >> 5;
    int lane = gid & 31;
    if (node >= N_NODES) return;

    int beg = g_off[node];
    int end = g_off[node + 1];

    float acc0 = 0.f, acc1 = 0.f, acc2 = 0.f, acc3 = 0.f;

    if (beg < end) {
        float sd = g_sdst[node];

        // pass 1: segment max of leaky_relu(t + sd)
        float mx = -FLT_MAX;
        for (int j = beg + lane; j < end; j += 32) {
            float x = g_tp[j] + sd;
            x = x > 0.f ? x : 0.01f * x;
            mx = fmaxf(mx, x);
        }
#pragma unroll
        for (int o = 16; o; o >>= 1) mx = fmaxf(mx, __shfl_xor_sync(0xffffffffu, mx, o));

        // pass 2: denominator
        float sum = 0.f;
        for (int j = beg + lane; j < end; j += 32) {
            float x = g_tp[j] + sd;
            x = x > 0.f ? x : 0.01f * x;
            sum += __expf(x - mx);
        }
#pragma unroll
        for (int o = 16; o; o >>= 1) sum += __shfl_xor_sync(0xffffffffu, sum, o);
        float inv = 1.0f / sum;   // sum >= 1 since the max element contributes exp(0)=1

        // pass 3: weighted gather of z[src] rows (lane owns 4 feature dims)
        for (int j0 = beg; j0 < end; j0 += 32) {
            int j = j0 + lane;
            float wgt = 0.f;
            int sidx = 0;
            if (j < end) {
                float x = g_tp[j] + sd;
                x = x > 0.f ? x : 0.01f * x;
                wgt = __expf(x - mx) * inv;
                sidx = g_srcp[j];
            }
            int cnt = end - j0;
            if (cnt > 32) cnt = 32;
            for (int q = 0; q < cnt; q++) {
                float al = __shfl_sync(0xffffffffu, wgt, q);
                int sq = __shfl_sync(0xffffffffu, sidx, q);
                float4 zv = *(const float4*)&g_z[sq * 128 + lane * 4];
                acc0 += al * zv.x;
                acc1 += al * zv.y;
                acc2 += al * zv.z;
                acc3 += al * zv.w;
            }
        }
    }

    float4 o4 = make_float4(acc0, acc1, acc2, acc3);
    *(float4*)&h[node * 128 + lane * 4] = o4;
}

// ---------------- launcher ----------------
extern "C" void kernel_launch(void* const* d_in, const int* in_sizes, int n_in,
                              void* d_out, int out_size) {
    const float* nfeats = (const float*)d_in[0];
    const float* efeats = (const float*)d_in[1];
    const float* W_fc   = (const float*)d_in[2];
    const float* W_attn = (const float*)d_in[3];
    const int*   src    = (const int*)d_in[4];
    const int*   dst    = (const int*)d_in[5];
    float* out = (float*)d_out;

    init_kernel<<<(N_NODES + 255) / 256, 256>>>();
    gemm_kernel<<<(N_NODES + 63) / 64, 256>>>(nfeats, W_fc);
    attn_proj_kernel<<<(N_NODES * 32 + 255) / 256, 256>>>(W_attn);
    edge_prep_kernel<<<(N_EDGES * 8 + 255) / 256, 256>>>(efeats, W_attn, src, dst);
    scan_kernel<<<1, 1024>>>();
    scatter_kernel<<<(N_EDGES + 255) / 256, 256>>>(src, dst);
    aggregate_kernel<<<(N_NODES * 32 + 255) / 256, 256>>>(out);
}

// round 2
// speedup vs baseline: 1.0683x; 1.0683x over previous
#include <cuda_runtime.h>
#include <math.h>
#include <float.h>

#define N_NODES 50000
#define N_EDGES 800000
#define DIM 128
#define EDIM 32

// ---------------- scratch (static device allocations) ----------------
__device__ float g_z[N_NODES * DIM];      // projected features
__device__ float g_ssrc[N_NODES];
__device__ float g_sdst[N_NODES];
__device__ int   g_cnt[N_NODES];
__device__ int   g_off[N_NODES + 1];
__device__ int   g_cur[N_NODES];
__device__ uint2 g_pair[N_EDGES];         // (src, bits(t)) permuted into CSR-by-dst order

__global__ void init_kernel() {
    int i = blockIdx.x * blockDim.x + threadIdx.x;
    if (i < N_NODES) g_cnt[i] = 0;
}

// ---------------- GEMM: z = nfeats @ W_fc^T, fused s_src/s_dst epilogue -------
// Block: 256 threads computes 64 rows x 128 cols. Each thread: 8 rows x 4 cols.
#define FMA4(ACC, S, B) { (ACC).x += (S)*(B).x; (ACC).y += (S)*(B).y; (ACC).z += (S)*(B).z; (ACC).w += (S)*(B).w; }
#define DOT4(A, B) ((A).x*(B).x + (A).y*(B).y + (A).z*(B).z + (A).w*(B).w)

__global__ __launch_bounds__(256) void gemm_kernel(const float* __restrict__ A,
                                                   const float* __restrict__ W,
                                                   const float* __restrict__ Wattn) {
    __shared__ __align__(16) float As[64 * 32];    // [row][kk]
    __shared__ __align__(16) float Bs[32 * 132];   // [kk][j], padded

    int tid = threadIdx.x;
    int i0 = blockIdx.x * 64;
    int tx = tid & 31;      // col group: cols tx*4 .. tx*4+3
    int ty = tid >> 5;      // row group: rows ty*8 .. ty*8+7

    float4 acc[8];
#pragma unroll
    for (int r = 0; r < 8; r++) acc[r] = make_float4(0.f, 0.f, 0.f, 0.f);

    for (int kc = 0; kc < 128; kc += 32) {
        // load A chunk: 64 rows x 32 k  (512 float4, 2 per thread)
#pragma unroll
        for (int t = 0; t < 2; t++) {
            int idx = tid + t * 256;
            int row = idx >> 3, c4 = idx & 7;
            int gr = i0 + row;
            float4 v = make_float4(0.f, 0.f, 0.f, 0.f);
            if (gr < N_NODES) v = *(const float4*)&A[gr * 128 + kc + c4 * 4];
            *(float4*)&As[row * 32 + c4 * 4] = v;
        }
        // load W chunk transposed: Bs[kk][j] = W[j][kc+kk]
#pragma unroll
        for (int t = 0; t < 4; t++) {
            int idx = tid + t * 256;
            int j = idx >> 3, k4 = idx & 7;
            float4 v = *(const float4*)&W[j * 128 + kc + k4 * 4];
            Bs[(k4 * 4 + 0) * 132 + j] = v.x;
            Bs[(k4 * 4 + 1) * 132 + j] = v.y;
            Bs[(k4 * 4 + 2) * 132 + j] = v.z;
            Bs[(k4 * 4 + 3) * 132 + j] = v.w;
        }
        __syncthreads();

#pragma unroll
        for (int kk = 0; kk < 32; kk += 4) {
            float4 b0 = *(const float4*)&Bs[(kk + 0) * 132 + tx * 4];
            float4 b1 = *(const float4*)&Bs[(kk + 1) * 132 + tx * 4];
            float4 b2 = *(const float4*)&Bs[(kk + 2) * 132 + tx * 4];
            float4 b3 = *(const float4*)&Bs[(kk + 3) * 132 + tx * 4];
#pragma unroll
            for (int r = 0; r < 8; r++) {
                float4 a = *(const float4*)&As[(ty * 8 + r) * 32 + kk];
                FMA4(acc[r], a.x, b0);
                FMA4(acc[r], a.y, b1);
                FMA4(acc[r], a.z, b2);
                FMA4(acc[r], a.w, b3);
            }
        }
        __syncthreads();
    }

    // epilogue: store z, and reduce s_src/s_dst per row across the warp
    float4 as4 = *(const float4*)&Wattn[tx * 4];               // a_src
    float4 ad4 = *(const float4*)&Wattn[DIM + EDIM + tx * 4];  // a_dst (offset 160)

#pragma unroll
    for (int r = 0; r < 8; r++) {
        int gr = i0 + ty * 8 + r;
        if (gr < N_NODES) *(float4*)&g_z[gr * 128 + tx * 4] = acc[r];
        float ps = DOT4(acc[r], as4);
        float pd = DOT4(acc[r], ad4);
#pragma unroll
        for (int o = 16; o; o >>= 1) {
            ps += __shfl_xor_sync(0xffffffffu, ps, o);
            pd += __shfl_xor_sync(0xffffffffu, pd, o);
        }
        if (tx == 0 && gr < N_NODES) { g_ssrc[gr] = ps; g_sdst[gr] = pd; }
    }
}

// ---------------- histogram of dst ----------------
__global__ __launch_bounds__(256) void hist_kernel(const int* __restrict__ dst) {
    int e = blockIdx.x * blockDim.x + threadIdx.x;
    if (e < N_EDGES) atomicAdd(&g_cnt[dst[e]], 1);
}

// ---------------- single-block scan: counts -> exclusive offsets ----------------
__global__ __launch_bounds__(1024) void scan_kernel() {
    __shared__ int ss[1024];
    int t = threadIdx.x;
    const int CH = (N_NODES + 1023) / 1024;   // 49
    int base = t * CH;
    int s = 0;
    for (int i = 0; i < CH; i++) {
        int idx = base + i;
        if (idx < N_NODES) s += g_cnt[idx];
    }
    ss[t] = s;
    __syncthreads();
    int incl = s;
    for (int off = 1; off < 1024; off <<= 1) {
        int v = (t >= off) ? ss[t - off] : 0;
        __syncthreads();
        incl += v;
        ss[t] = incl;
        __syncthreads();
    }
    int run = incl - s;   // exclusive prefix
    for (int i = 0; i < CH; i++) {
        int idx = base + i;
        if (idx < N_NODES) {
            g_off[idx] = run;
            g_cur[idx] = run;
            run += g_cnt[idx];
        }
    }
    if (t == 1023) g_off[N_NODES] = run;
}

// ---------------- fused per-edge score + CSR scatter ----------------
// 8 lanes per edge, float4 per lane over the 32 edge features.
__global__ __launch_bounds__(256) void edge_fused_kernel(const float* __restrict__ efeats,
                                                         const float* __restrict__ Wattn,
                                                         const int* __restrict__ src,
                                                         const int* __restrict__ dst) {
    int gid = blockIdx.x * blockDim.x + threadIdx.x;
    int e = gid >> 3;
    int l = gid & 7;
    if (e >= N_EDGES) return;
    float4 ev = *(const float4*)&efeats[e * EDIM + l * 4];
    float4 av = *(const float4*)&Wattn[DIM + l * 4];   // a_e (offset 128)
    float p = DOT4(ev, av);
    p += __shfl_xor_sync(0xffffffffu, p, 4);
    p += __shfl_xor_sync(0xffffffffu, p, 2);
    p += __shfl_xor_sync(0xffffffffu, p, 1);
    if (l == 0) {
        int s = src[e];
        int d = dst[e];
        float t = p + g_ssrc[s];
        int pos = atomicAdd(&g_cur[d], 1);
        g_pair[pos] = make_uint2((unsigned)s, __float_as_uint(t));
    }
}

// ---------------- warp-per-node softmax + aggregation ----------------
__global__ __launch_bounds__(256) void aggregate_kernel(float* __restrict__ h) {
    int gid = blockIdx.x * blockDim.x + threadIdx.x;
    int node = gid >> 5;
    int lane = gid & 31;
    if (node >= N_NODES) return;

    int beg = g_off[node];
    int end = g_off[node + 1];

    float acc0 = 0.f, acc1 = 0.f, acc2 = 0.f, acc3 = 0.f;

    if (beg < end) {
        float sd = g_sdst[node];

        // pass 1: segment max of leaky_relu(t + sd)
        float mx = -FLT_MAX;
        for (int j = beg + lane; j < end; j += 32) {
            float x = __uint_as_float(g_pair[j].y) + sd;
            x = x > 0.f ? x : 0.01f * x;
            mx = fmaxf(mx, x);
        }
#pragma unroll
        for (int o = 16; o; o >>= 1) mx = fmaxf(mx, __shfl_xor_sync(0xffffffffu, mx, o));

        // pass 2: denominator
        float sum = 0.f;
        for (int j = beg + lane; j < end; j += 32) {
            float x = __uint_as_float(g_pair[j].y) + sd;
            x = x > 0.f ? x : 0.01f * x;
            sum += __expf(x - mx);
        }
#pragma unroll
        for (int o = 16; o; o >>= 1) sum += __shfl_xor_sync(0xffffffffu, sum, o);
        float inv = 1.0f / sum;   // sum >= 1: the max element contributes exp(0)=1

        // pass 3: weighted gather of z[src] rows (lane owns 4 feature dims).
        // Unrolled x4 so 4 independent float4 gathers are in flight (MLP=4).
        for (int j0 = beg; j0 < end; j0 += 32) {
            int j = j0 + lane;
            float wgt = 0.f;
            int sidx = 0;
            if (j < end) {
                uint2 pr = g_pair[j];
                float x = __uint_as_float(pr.y) + sd;
                x = x > 0.f ? x : 0.01f * x;
                wgt = __expf(x - mx);
                sidx = (int)pr.x;
            }
            int cnt = end - j0;
            if (cnt > 32) cnt = 32;
            int q = 0;
            for (; q + 4 <= cnt; q += 4) {
                float a0 = __shfl_sync(0xffffffffu, wgt, q + 0);
                float a1 = __shfl_sync(0xffffffffu, wgt, q + 1);
                float a2 = __shfl_sync(0xffffffffu, wgt, q + 2);
                float a3 = __shfl_sync(0xffffffffu, wgt, q + 3);
                int s0 = __shfl_sync(0xffffffffu, sidx, q + 0);
                int s1 = __shfl_sync(0xffffffffu, sidx, q + 1);
                int s2 = __shfl_sync(0xffffffffu, sidx, q + 2);
                int s3 = __shfl_sync(0xffffffffu, sidx, q + 3);
                float4 z0 = *(const float4*)&g_z[s0 * 128 + lane * 4];
                float4 z1 = *(const float4*)&g_z[s1 * 128 + lane * 4];
                float4 z2 = *(const float4*)&g_z[s2 * 128 + lane * 4];
                float4 z3 = *(const float4*)&g_z[s3 * 128 + lane * 4];
                acc0 += a0 * z0.x; acc1 += a0 * z0.y; acc2 += a0 * z0.z; acc3 += a0 * z0.w;
                acc0 += a1 * z1.x; acc1 += a1 * z1.y; acc2 += a1 * z1.z; acc3 += a1 * z1.w;
                acc0 += a2 * z2.x; acc1 += a2 * z2.y; acc2 += a2 * z2.z; acc3 += a2 * z2.w;
                acc0 += a3 * z3.x; acc1 += a3 * z3.y; acc2 += a3 * z3.z; acc3 += a3 * z3.w;
            }
            for (; q < cnt; q++) {
                float al = __shfl_sync(0xffffffffu, wgt, q);
                int sq = __shfl_sync(0xffffffffu, sidx, q);
                float4 zv = *(const float4*)&g_z[sq * 128 + lane * 4];
                acc0 += al * zv.x; acc1 += al * zv.y; acc2 += al * zv.z; acc3 += al * zv.w;
            }
        }
        acc0 *= inv; acc1 *= inv; acc2 *= inv; acc3 *= inv;
    }

    float4 o4 = make_float4(acc0, acc1, acc2, acc3);
    *(float4*)&h[node * 128 + lane * 4] = o4;
}

// ---------------- launcher ----------------
extern "C" void kernel_launch(void* const* d_in, const int* in_sizes, int n_in,
                              void* d_out, int out_size) {
    const float* nfeats = (const float*)d_in[0];
    const float* efeats = (const float*)d_in[1];
    const float* W_fc   = (const float*)d_in[2];
    const float* W_attn = (const float*)d_in[3];
    const int*   src    = (const int*)d_in[4];
    const int*   dst    = (const int*)d_in[5];
    float* out = (float*)d_out;

    init_kernel<<<(N_NODES + 255) / 256, 256>>>();
    gemm_kernel<<<(N_NODES + 63) / 64, 256>>>(nfeats, W_fc, W_attn);
    hist_kernel<<<(N_EDGES + 255) / 256, 256>>>(dst);
    scan_kernel<<<1, 1024>>>();
    edge_fused_kernel<<<(N_EDGES * 8 + 255) / 256, 256>>>(efeats, W_attn, src, dst);
    aggregate_kernel<<<(N_NODES * 32 + 255) / 256, 256>>>(out);
}

// round 3
// speedup vs baseline: 1.5851x; 1.4838x over previous
#include <cuda_runtime.h>
#include <math.h>
#include <float.h>

#define N_NODES 50000
#define N_EDGES 800000
#define DIM 128
#define EDIM 32
#define NB_SCAN ((N_NODES + 1023) / 1024)   // 49 scan blocks

// ---------------- scratch (static device allocations) ----------------
__device__ float g_z[N_NODES * DIM];      // projected features
__device__ float g_ssrc[N_NODES];
__device__ float g_sdst[N_NODES];
__device__ int   g_cnt[N_NODES];
__device__ int   g_lex[N_NODES];          // block-local exclusive scan
__device__ int   g_bsum[64];
__device__ int   g_bpre[64];
__device__ int   g_off[N_NODES + 1];
__device__ int   g_cur[N_NODES];
__device__ uint2 g_pair[N_EDGES];         // (src, bits(t)) permuted into CSR-by-dst order

__global__ void init_kernel() {
    int i = blockIdx.x * blockDim.x + threadIdx.x;
    if (i < N_NODES) g_cnt[i] = 0;
    if (i == 0) g_off[N_NODES] = N_EDGES;  // total is a compile-time constant
}

// ---------------- GEMM: z = nfeats @ W_fc^T, fused s_src/s_dst epilogue -------
// Block: 256 threads computes 64 rows x 128 cols. Each thread: 8 rows x 4 cols.
#define FMA4(ACC, S, B) { (ACC).x += (S)*(B).x; (ACC).y += (S)*(B).y; (ACC).z += (S)*(B).z; (ACC).w += (S)*(B).w; }
#define DOT4(A, B) ((A).x*(B).x + (A).y*(B).y + (A).z*(B).z + (A).w*(B).w)

__global__ __launch_bounds__(256) void gemm_kernel(const float* __restrict__ A,
                                                   const float* __restrict__ W,
                                                   const float* __restrict__ Wattn) {
    __shared__ __align__(16) float As[64 * 32];    // [row][kk]
    __shared__ __align__(16) float Bs[32 * 132];   // [kk][j], padded

    int tid = threadIdx.x;
    int i0 = blockIdx.x * 64;
    int tx = tid & 31;      // col group: cols tx*4 .. tx*4+3
    int ty = tid >> 5;      // row group: rows ty*8 .. ty*8+7

    float4 acc[8];
#pragma unroll
    for (int r = 0; r < 8; r++) acc[r] = make_float4(0.f, 0.f, 0.f, 0.f);

    for (int kc = 0; kc < 128; kc += 32) {
#pragma unroll
        for (int t = 0; t < 2; t++) {
            int idx = tid + t * 256;
            int row = idx >> 3, c4 = idx & 7;
            int gr = i0 + row;
            float4 v = make_float4(0.f, 0.f, 0.f, 0.f);
            if (gr < N_NODES) v = *(const float4*)&A[gr * 128 + kc + c4 * 4];
            *(float4*)&As[row * 32 + c4 * 4] = v;
        }
#pragma unroll
        for (int t = 0; t < 4; t++) {
            int idx = tid + t * 256;
            int j = idx >> 3, k4 = idx & 7;
            float4 v = *(const float4*)&W[j * 128 + kc + k4 * 4];
            Bs[(k4 * 4 + 0) * 132 + j] = v.x;
            Bs[(k4 * 4 + 1) * 132 + j] = v.y;
            Bs[(k4 * 4 + 2) * 132 + j] = v.z;
            Bs[(k4 * 4 + 3) * 132 + j] = v.w;
        }
        __syncthreads();

#pragma unroll
        for (int kk = 0; kk < 32; kk += 4) {
            float4 b0 = *(const float4*)&Bs[(kk + 0) * 132 + tx * 4];
            float4 b1 = *(const float4*)&Bs[(kk + 1) * 132 + tx * 4];
            float4 b2 = *(const float4*)&Bs[(kk + 2) * 132 + tx * 4];
            float4 b3 = *(const float4*)&Bs[(kk + 3) * 132 + tx * 4];
#pragma unroll
            for (int r = 0; r < 8; r++) {
                float4 a = *(const float4*)&As[(ty * 8 + r) * 32 + kk];
                FMA4(acc[r], a.x, b0);
                FMA4(acc[r], a.y, b1);
                FMA4(acc[r], a.z, b2);
                FMA4(acc[r], a.w, b3);
            }
        }
        __syncthreads();
    }

    // epilogue: store z, and reduce s_src/s_dst per row across the warp
    float4 as4 = *(const float4*)&Wattn[tx * 4];               // a_src
    float4 ad4 = *(const float4*)&Wattn[DIM + EDIM + tx * 4];  // a_dst (offset 160)

#pragma unroll
    for (int r = 0; r < 8; r++) {
        int gr = i0 + ty * 8 + r;
        if (gr < N_NODES) *(float4*)&g_z[gr * 128 + tx * 4] = acc[r];
        float ps = DOT4(acc[r], as4);
        float pd = DOT4(acc[r], ad4);
#pragma unroll
        for (int o = 16; o; o >>= 1) {
            ps += __shfl_xor_sync(0xffffffffu, ps, o);
            pd += __shfl_xor_sync(0xffffffffu, pd, o);
        }
        if (tx == 0 && gr < N_NODES) { g_ssrc[gr] = ps; g_sdst[gr] = pd; }
    }
}

// ---------------- histogram of dst ----------------
__global__ __launch_bounds__(256) void hist_kernel(const int* __restrict__ dst) {
    int e = blockIdx.x * blockDim.x + threadIdx.x;
    if (e < N_EDGES) atomicAdd(&g_cnt[dst[e]], 1);
}

// ---------------- parallel scan, phase 1: block-local exclusive scan ----------
__global__ __launch_bounds__(1024) void scan1_kernel() {
    __shared__ int ws[32];
    int t = threadIdx.x, b = blockIdx.x;
    int i = b * 1024 + t;
    int lane = t & 31, w = t >> 5;
    int c = (i < N_NODES) ? g_cnt[i] : 0;
    int v = c;
#pragma unroll
    for (int o = 1; o < 32; o <<= 1) {
        int n = __shfl_up_sync(0xffffffffu, v, o);
        if (lane >= o) v += n;
    }
    if (lane == 31) ws[w] = v;
    __syncthreads();
    if (w == 0) {
        int s = ws[lane];
#pragma unroll
        for (int o = 1; o < 32; o <<= 1) {
            int n = __shfl_up_sync(0xffffffffu, s, o);
            if (lane >= o) s += n;
        }
        ws[lane] = s;
    }
    __syncthreads();
    int pre = (w > 0) ? ws[w - 1] : 0;
    if (i < N_NODES) g_lex[i] = pre + v - c;   // exclusive within block
    if (t == 0) g_bsum[b] = ws[31];            // block total
}

// ---------------- phase 2: exclusive scan of block sums (one tiny block) ------
__global__ __launch_bounds__(64) void scan2_kernel() {
    __shared__ int ss[64];
    int t = threadIdx.x;
    int v = (t < NB_SCAN) ? g_bsum[t] : 0;
    ss[t] = v;
    __syncthreads();
    int incl = v;
#pragma unroll
    for (int o = 1; o < 64; o <<= 1) {
        int n = (t >= o) ? ss[t - o] : 0;
        __syncthreads();
        incl += n;
        ss[t] = incl;
        __syncthreads();
    }
    if (t < NB_SCAN) g_bpre[t] = incl - v;     // exclusive
}

// ---------------- phase 3: add block prefix -> offsets ----------------
__global__ __launch_bounds__(256) void scan3_kernel() {
    int i = blockIdx.x * blockDim.x + threadIdx.x;
    if (i < N_NODES) {
        int off = g_lex[i] + g_bpre[i >> 10];
        g_off[i] = off;
        g_cur[i] = off;
    }
}

// ---------------- fused per-edge score + CSR scatter ----------------
// 8 lanes per edge, float4 per lane over the 32 edge features.
__global__ __launch_bounds__(256) void edge_fused_kernel(const float* __restrict__ efeats,
                                                         const float* __restrict__ Wattn,
                                                         const int* __restrict__ src,
                                                         const int* __restrict__ dst) {
    int gid = blockIdx.x * blockDim.x + threadIdx.x;
    int e = gid >> 3;
    int l = gid & 7;
    if (e >= N_EDGES) return;
    float4 ev = *(const float4*)&efeats[e * EDIM + l * 4];
    float4 av = *(const float4*)&Wattn[DIM + l * 4];   // a_e (offset 128)
    float p = DOT4(ev, av);
    p += __shfl_xor_sync(0xffffffffu, p, 4);
    p += __shfl_xor_sync(0xffffffffu, p, 2);
    p += __shfl_xor_sync(0xffffffffu, p, 1);
    if (l == 0) {
        int s = src[e];
        int d = dst[e];
        float t = p + g_ssrc[s];
        int pos = atomicAdd(&g_cur[d], 1);
        g_pair[pos] = make_uint2((unsigned)s, __float_as_uint(t));
    }
}

// ---------------- warp-per-node softmax + aggregation ----------------
__global__ __launch_bounds__(256) void aggregate_kernel(float* __restrict__ h) {
    int gid = blockIdx.x * blockDim.x + threadIdx.x;
    int node = gid >> 5;
    int lane = gid & 31;
    if (node >= N_NODES) return;

    int beg = g_off[node];
    int end = g_off[node + 1];

    float acc0 = 0.f, acc1 = 0.f, acc2 = 0.f, acc3 = 0.f;

    if (beg < end) {
        float sd = g_sdst[node];

        // pass 1: segment max of leaky_relu(t + sd)
        float mx = -FLT_MAX;
        for (int j = beg + lane; j < end; j += 32) {
            float x = __uint_as_float(g_pair[j].y) + sd;
            x = x > 0.f ? x : 0.01f * x;
            mx = fmaxf(mx, x);
        }
#pragma unroll
        for (int o = 16; o; o >>= 1) mx = fmaxf(mx, __shfl_xor_sync(0xffffffffu, mx, o));

        // pass 2: denominator
        float sum = 0.f;
        for (int j = beg + lane; j < end; j += 32) {
            float x = __uint_as_float(g_pair[j].y) + sd;
            x = x > 0.f ? x : 0.01f * x;
            sum += __expf(x - mx);
        }
#pragma unroll
        for (int o = 16; o; o >>= 1) sum += __shfl_xor_sync(0xffffffffu, sum, o);
        float inv = 1.0f / sum;   // sum >= 1: the max element contributes exp(0)=1

        // pass 3: weighted gather of z[src] rows (lane owns 4 feature dims).
        // Unrolled x4 so 4 independent float4 gathers are in flight (MLP=4).
        for (int j0 = beg; j0 < end; j0 += 32) {
            int j = j0 + lane;
            float wgt = 0.f;
            int sidx = 0;
            if (j < end) {
                uint2 pr = g_pair[j];
                float x = __uint_as_float(pr.y) + sd;
                x = x > 0.f ? x : 0.01f * x;
                wgt = __expf(x - mx);
                sidx = (int)pr.x;
            }
            int cnt = end - j0;
            if (cnt > 32) cnt = 32;
            int q = 0;
            for (; q + 4 <= cnt; q += 4) {
                float a0 = __shfl_sync(0xffffffffu, wgt, q + 0);
                float a1 = __shfl_sync(0xffffffffu, wgt, q + 1);
                float a2 = __shfl_sync(0xffffffffu, wgt, q + 2);
                float a3 = __shfl_sync(0xffffffffu, wgt, q + 3);
                int s0 = __shfl_sync(0xffffffffu, sidx, q + 0);
                int s1 = __shfl_sync(0xffffffffu, sidx, q + 1);
                int s2 = __shfl_sync(0xffffffffu, sidx, q + 2);
                int s3 = __shfl_sync(0xffffffffu, sidx, q + 3);
                float4 z0 = *(const float4*)&g_z[s0 * 128 + lane * 4];
                float4 z1 = *(const float4*)&g_z[s1 * 128 + lane * 4];
                float4 z2 = *(const float4*)&g_z[s2 * 128 + lane * 4];
                float4 z3 = *(const float4*)&g_z[s3 * 128 + lane * 4];
                acc0 += a0 * z0.x; acc1 += a0 * z0.y; acc2 += a0 * z0.z; acc3 += a0 * z0.w;
                acc0 += a1 * z1.x; acc1 += a1 * z1.y; acc2 += a1 * z1.z; acc3 += a1 * z1.w;
                acc0 += a2 * z2.x; acc1 += a2 * z2.y; acc2 += a2 * z2.z; acc3 += a2 * z2.w;
                acc0 += a3 * z3.x; acc1 += a3 * z3.y; acc2 += a3 * z3.z; acc3 += a3 * z3.w;
            }
            for (; q < cnt; q++) {
                float al = __shfl_sync(0xffffffffu, wgt, q);
                int sq = __shfl_sync(0xffffffffu, sidx, q);
                float4 zv = *(const float4*)&g_z[sq * 128 + lane * 4];
                acc0 += al * zv.x; acc1 += al * zv.y; acc2 += al * zv.z; acc3 += al * zv.w;
            }
        }
        acc0 *= inv; acc1 *= inv; acc2 *= inv; acc3 *= inv;
    }

    float4 o4 = make_float4(acc0, acc1, acc2, acc3);
    *(float4*)&h[node * 128 + lane * 4] = o4;
}

// ---------------- launcher ----------------
extern "C" void kernel_launch(void* const* d_in, const int* in_sizes, int n_in,
                              void* d_out, int out_size) {
    const float* nfeats = (const float*)d_in[0];
    const float* efeats = (const float*)d_in[1];
    const float* W_fc   = (const float*)d_in[2];
    const float* W_attn = (const float*)d_in[3];
    const int*   src    = (const int*)d_in[4];
    const int*   dst    = (const int*)d_in[5];
    float* out = (float*)d_out;

    init_kernel<<<(N_NODES + 255) / 256, 256>>>();
    gemm_kernel<<<(N_NODES + 63) / 64, 256>>>(nfeats, W_fc, W_attn);
    hist_kernel<<<(N_EDGES + 255) / 256, 256>>>(dst);
    scan1_kernel<<<NB_SCAN, 1024>>>();
    scan2_kernel<<<1, 64>>>();
    scan3_kernel<<<(N_NODES + 255) / 256, 256>>>();
    edge_fused_kernel<<<(N_EDGES * 8 + 255) / 256, 256>>>(efeats, W_attn, src, dst);
    aggregate_kernel<<<(N_NODES * 32 + 255) / 256, 256>>>(out);
}